// round 7
// baseline (speedup 1.0000x reference)
#include <cuda_runtime.h>
#include <math_constants.h>

#define NF 8
#define NQ 300
#define HH 96
#define WW 96
#define HW (HH*WW)        // 9216
#define FHW (NF*HW)       // 73728
#define ALPHA_C 0.25f
#define EPSV 1e-8f

// bits per (b,f,row,chunk): {tmask bits, vpad bits}
__device__ uint2 g_meta[16][HH*3];
// per (b,q,half): 10 partial sums
__device__ float g_scr[2*NQ][2][10];

__device__ __forceinline__ float tanh_hw(float x) {
    float y;
    asm("tanh.approx.f32 %0, %1;" : "=f"(y) : "f"(x));
    return y;
}
__device__ __forceinline__ float sigmoid_hw(float x) {
    return fmaf(0.5f, tanh_hw(0.5f * x), 0.5f);
}
__device__ __forceinline__ float sigmoid_fast(float x) {
    float a = fabsf(x);
    float u = __expf(-a);
    float r = __fdividef(1.0f, 1.0f + u);
    return (x >= 0.0f) ? r : u * r;
}
__device__ __forceinline__ float warp_sum(float v) {
    #pragma unroll
    for (int o = 16; o; o >>= 1) v += __shfl_xor_sync(0xffffffff, v, o);
    return v;
}
__device__ __forceinline__ float warp_max(float v) {
    #pragma unroll
    for (int o = 16; o; o >>= 1) v = fmaxf(v, __shfl_xor_sync(0xffffffff, v, o));
    return v;
}

// ---------------------------------------------------------------------------
// Prep: ballots only. grid = 16*12 = 192 blocks, 128 threads; warp owns 2 rows.
// ---------------------------------------------------------------------------
__global__ __launch_bounds__(128) void prep_kernel(
    const float* __restrict__ tmask, const unsigned char* __restrict__ vpad)
{
    int bf = blockIdx.x / 12;       // 0..15
    int rg = blockIdx.x % 12;       // row group of 8
    int b = bf >> 3;
    int tid = threadIdx.x;
    int wp = tid >> 5, lane = tid & 31;
    const float* base = tmask + (size_t)bf * HW;
    const unsigned char* vb = vpad + (size_t)b * HW;

    #pragma unroll
    for (int rr = 0; rr < 2; ++rr) {
        int row = rg * 8 + wp * 2 + rr;
        const float* rp = base + row * WW;
        const unsigned char* vr = vb + row * WW;
        float v0 = rp[lane], v1 = rp[32 + lane], v2 = rp[64 + lane];
        unsigned char q0 = vr[lane], q1 = vr[32 + lane], q2 = vr[64 + lane];
        unsigned t0 = __ballot_sync(0xffffffff, v0 != 0.0f);
        unsigned t1 = __ballot_sync(0xffffffff, v1 != 0.0f);
        unsigned t2 = __ballot_sync(0xffffffff, v2 != 0.0f);
        unsigned p0 = __ballot_sync(0xffffffff, q0 != 0);
        unsigned p1 = __ballot_sync(0xffffffff, q1 != 0);
        unsigned p2 = __ballot_sync(0xffffffff, q2 != 0);
        if (lane == 0) {
            g_meta[bf][row * 3 + 0] = make_uint2(t0, p0);
            g_meta[bf][row * 3 + 1] = make_uint2(t1, p1);
            g_meta[bf][row * 3 + 2] = make_uint2(t2, p2);
        }
    }
}

// ---------------------------------------------------------------------------
// Cost partials: one block per (b, q, half). 384 threads = 12 warps.
// Block processes 4 frames. Warp wp owns rows 8*wp..8*wp+7 of each frame.
// ---------------------------------------------------------------------------
__global__ __launch_bounds__(384, 3) void cost_kernel(
    const float* __restrict__ masks)    // (2,8,300,96,96)
{
    int blk = blockIdx.x;               // 0..1199
    int bq = blk >> 1, half = blk & 1;
    int b = bq / NQ, q = bq % NQ;
    int f0 = half * 4;
    int tid = threadIdx.x;
    int warp = tid >> 5, lane = tid & 31;

    __shared__ float rowFinal[4 * HH];            // 1.5 KB
    __shared__ float colAll[4 * 3 * 384];         // 18 KB: [f][chunk][warp][lane]
    __shared__ unsigned orAll[4 * 3 * 12];        // target col-OR words
    __shared__ float red[12][10];

    float facc = 0.0f, nacc = 0.0f, sacc = 0.0f;

    #pragma unroll 1
    for (int f = 0; f < 4; ++f) {
        const float* mb = masks + (size_t)((b * NF + f0 + f) * NQ + q) * HW + lane;
        const uint2* mt = g_meta[b * NF + f0 + f];
        float c0 = -CUDART_INF_F, c1 = -CUDART_INF_F, c2 = -CUDART_INF_F;
        unsigned o0 = 0u, o1 = 0u, o2 = 0u;
        #pragma unroll 2
        for (int r = 0; r < 8; ++r) {
            int row = warp * 8 + r;
            uint2 m0 = mt[row * 3 + 0];
            uint2 m1 = mt[row * 3 + 1];
            uint2 m2 = mt[row * 3 + 2];
            const float* rp = mb + row * WW;
            float x0 = rp[0], x1 = rp[32], x2 = rp[64];
            if ((m0.y >> lane) & 1) x0 = 0.0f;
            if ((m1.y >> lane) & 1) x1 = 0.0f;
            if ((m2.y >> lane) & 1) x2 = 0.0f;
            o0 |= m0.x; o1 |= m1.x; o2 |= m2.x;

            #pragma unroll
            for (int c = 0; c < 3; ++c) {
                float x = (c == 0) ? x0 : (c == 1) ? x1 : x2;
                unsigned tw = (c == 0) ? m0.x : (c == 1) ? m1.x : m2.x;
                bool tb = (tw >> lane) & 1;
                float p = sigmoid_hw(x);
                float omp_ = 1.0f - p;
                float pa = fmaxf(p, omp_);
                float lg = -__logf(pa);
                float ce = fmaxf(tb ? -x : x, 0.0f) + lg;
                float omp = tb ? omp_ : p;
                float at = tb ? 0.25f : 0.75f;
                facc = fmaf(at * ce * omp, omp, facc);
                sacc += p;
                if (tb) nacc += p;
            }
            c0 = fmaxf(c0, x0); c1 = fmaxf(c1, x1); c2 = fmaxf(c2, x2);
            float rm = warp_max(fmaxf(fmaxf(x0, x1), x2));
            if (lane == 0) rowFinal[f * HH + row] = rm;
        }
        colAll[((f * 3 + 0) * 12 + warp) * 32 + lane] = c0;
        colAll[((f * 3 + 1) * 12 + warp) * 32 + lane] = c1;
        colAll[((f * 3 + 2) * 12 + warp) * 32 + lane] = c2;
        if (lane == 0) {
            orAll[(f * 3 + 0) * 12 + warp] = o0;
            orAll[(f * 3 + 1) * 12 + warp] = o1;
            orAll[(f * 3 + 2) * 12 + warp] = o2;
        }
    }
    __syncthreads();

    // projection partials + target stats from bits: 384 rows + 384 cols, 1 each
    float sx = 0, nx = 0, sy = 0, ny = 0, tsum = 0, txs = 0, tys = 0;
    {
        int f = tid / 96, j = tid % 96;
        // row side: (f, row=j)
        const uint2* mt = g_meta[b * NF + f0 + f];
        uint2 w0 = mt[j * 3 + 0], w1 = mt[j * 3 + 1], w2 = mt[j * 3 + 2];
        tsum = (float)(__popc(w0.x) + __popc(w1.x) + __popc(w2.x));
        float tgx = ((w0.x | w1.x | w2.x) != 0u) ? 1.0f : 0.0f;
        float px = sigmoid_fast(rowFinal[f * HH + j]);
        sx = px; nx = px * tgx; txs = tgx;
        // col side: (f, col=j)
        int c = j >> 5, l = j & 31;
        const float* cp = &colAll[((f * 3 + c) * 12) * 32 + l];
        const unsigned* op = &orAll[(f * 3 + c) * 12];
        float m = cp[0];
        unsigned ow = op[0];
        #pragma unroll
        for (int wp = 1; wp < 12; ++wp) { m = fmaxf(m, cp[wp * 32]); ow |= op[wp]; }
        float tgy = ((ow >> l) & 1u) ? 1.0f : 0.0f;
        float py = sigmoid_fast(m);
        sy = py; ny = py * tgy; tys = tgy;
    }

    float v0 = warp_sum(facc), v1 = warp_sum(nacc), v2 = warp_sum(sacc);
    float v3 = warp_sum(sx),   v4 = warp_sum(nx);
    float v5 = warp_sum(sy),   v6 = warp_sum(ny);
    float v7 = warp_sum(tsum), v8 = warp_sum(txs), v9 = warp_sum(tys);
    if (lane == 0) {
        red[warp][0] = v0; red[warp][1] = v1; red[warp][2] = v2;
        red[warp][3] = v3; red[warp][4] = v4; red[warp][5] = v5; red[warp][6] = v6;
        red[warp][7] = v7; red[warp][8] = v8; red[warp][9] = v9;
    }
    __syncthreads();
    if (warp == 0 && lane < 10) {
        float t = 0;
        #pragma unroll
        for (int i = 0; i < 12; ++i) t += red[i][lane];
        g_scr[bq][half][lane] = t;
    }
}

// ---------------------------------------------------------------------------
// Combine: per query, merge halves + cheap epilogue. grid=2, block=300
// ---------------------------------------------------------------------------
__global__ __launch_bounds__(512) void combine_kernel(
    const float* __restrict__ logits,
    const float* __restrict__ boxes,
    const float* __restrict__ tbox,
    const int*   __restrict__ tvalid,
    float* __restrict__ C)
{
    int b = blockIdx.x;
    int q = threadIdx.x;
    if (q >= NQ) return;
    int bq = b * NQ + q;

    float A[10];
    #pragma unroll
    for (int i = 0; i < 10; ++i) A[i] = g_scr[bq][0][i] + g_scr[bq][1][i];

    float cost_mask = A[0] / (float)FHW;
    float cost_dice = -((2.0f * A[1] + 1.0f) / (A[2] + A[7] + 1.0f));
    float dx = (2.0f * A[4] + 1.0f) / (A[3] + A[8] + 1.0f);
    float dy = (2.0f * A[6] + 1.0f) / (A[5] + A[9] + 1.0f);
    float cost_proj = -0.5f * (dy + dx);

    float cls = 0, wsum = 0, bbox = 0, giou = 0;
    #pragma unroll
    for (int f = 0; f < NF; ++f) {
        float lg = logits[(b * NF + f) * NQ + q];
        float p = sigmoid_fast(lg);
        float neg = (1.0f - ALPHA_C) * p * p * (-__logf(1.0f - p + EPSV));
        float pos = ALPHA_C * (1.0f - p) * (1.0f - p) * (-__logf(p + EPSV));
        float wv = (tvalid[b * NF + f] != 0) ? 1.0f : 0.0f;
        cls += (pos - neg) * wv; wsum += wv;

        const float* bx = boxes + (size_t)((b * NF + f) * NQ + q) * 4;
        const float* tx = tbox + (size_t)(b * NF + f) * 4;
        bbox += fabsf(bx[0]-tx[0]) + fabsf(bx[1]-tx[1]) + fabsf(bx[2]-tx[2]) + fabsf(bx[3]-tx[3]);

        float sx0 = bx[0]-0.5f*bx[2], sy0 = bx[1]-0.5f*bx[3];
        float sx1 = bx[0]+0.5f*bx[2], sy1 = bx[1]+0.5f*bx[3];
        float tx0 = tx[0]-0.5f*tx[2], ty0 = tx[1]-0.5f*tx[3];
        float tx1 = tx[0]+0.5f*tx[2], ty1 = tx[1]+0.5f*tx[3];
        float a1 = (sx1-sx0)*(sy1-sy0);
        float a2 = (tx1-tx0)*(ty1-ty0);
        float iw = fmaxf(fminf(sx1,tx1) - fmaxf(sx0,tx0), 0.0f);
        float ih = fmaxf(fminf(sy1,ty1) - fmaxf(sy0,ty0), 0.0f);
        float inter = iw * ih;
        float uni = a1 + a2 - inter;
        float iou = inter / uni;
        float cw = fmaxf(fmaxf(sx1,tx1) - fminf(sx0,tx0), 0.0f);
        float ch = fmaxf(fmaxf(sy1,ty1) - fminf(sy0,ty0), 0.0f);
        float ac = cw * ch;
        giou += -(iou - (ac - uni) / ac);
    }
    float cost_class = cls / wsum;
    float cost_bbox  = bbox * (1.0f / NF);
    float cost_giou  = giou * (1.0f / NF);

    C[bq] = cost_class + cost_bbox + cost_giou + cost_mask + cost_dice + cost_proj;
}

// ---------------------------------------------------------------------------
// Argmin over queries per batch + tail writes. grid=2, block=256
// ---------------------------------------------------------------------------
__global__ void argmin_kernel(const float* __restrict__ C, float* __restrict__ out, int out_size) {
    int b = blockIdx.x;
    int tid = threadIdx.x;
    float best = CUDART_INF_F; int bi = NQ;
    for (int q = tid; q < NQ; q += blockDim.x) {
        float v = C[b * NQ + q];
        if (v < best || (v == best && q < bi)) { best = v; bi = q; }
    }
    #pragma unroll
    for (int o = 16; o; o >>= 1) {
        float ov = __shfl_down_sync(0xffffffff, best, o);
        int   oi = __shfl_down_sync(0xffffffff, bi,   o);
        if (ov < best || (ov == best && oi < bi)) { best = ov; bi = oi; }
    }
    __shared__ float sv[8]; __shared__ int si[8];
    int wid = tid >> 5, lane = tid & 31;
    if (lane == 0) { sv[wid] = best; si[wid] = bi; }
    __syncthreads();
    if (tid == 0) {
        int nw = blockDim.x >> 5;
        for (int i = 1; i < nw; ++i) {
            if (sv[i] < best || (sv[i] == best && si[i] < bi)) { best = sv[i]; bi = si[i]; }
        }
        if (out_size >= 608) {
            long long* op = (long long*)(out + 600);
            op[b] = (long long)bi;
            op[2 + b] = 0ll;
            if (b == 0) for (int i = 608; i < out_size; ++i) out[i] = 0.0f;
        } else if (out_size >= 604) {
            out[600 + b] = (float)bi;
            out[602 + b] = 0.0f;
            if (b == 0) for (int i = 604; i < out_size; ++i) out[i] = 0.0f;
        } else {
            if (b == 0) for (int i = 600; i < out_size; ++i) out[i] = 0.0f;
        }
    }
}

extern "C" void kernel_launch(void* const* d_in, const int* in_sizes, int n_in,
                              void* d_out, int out_size) {
    const float* logits = (const float*)d_in[0];
    const float* boxes  = (const float*)d_in[1];
    const float* masks  = (const float*)d_in[2];
    const float* tmask  = (const float*)d_in[3];
    const float* tbox   = (const float*)d_in[4];
    const int*   tvalid = (const int*)d_in[5];
    const unsigned char* vpad = (const unsigned char*)d_in[6];
    float* out = (float*)d_out;

    prep_kernel<<<192, 128>>>(tmask, vpad);
    cost_kernel<<<4 * NQ, 384>>>(masks);
    combine_kernel<<<2, 512>>>(logits, boxes, tbox, tvalid, out);
    argmin_kernel<<<2, 256>>>(out, out, out_size);
}

// round 8
// speedup vs baseline: 1.1949x; 1.1949x over previous
#include <cuda_runtime.h>
#include <math_constants.h>

#define NF 8
#define NQ 300
#define HH 96
#define WW 96
#define HW (HH*WW)        // 9216
#define FHW (NF*HW)       // 73728
#define ALPHA_C 0.25f
#define EPSV 1e-8f

// bits per (b,f,row,chunk): {tmask bits, vpad bits}
__device__ uint2 g_meta[16][HH*3];
__device__ unsigned g_done;

__device__ __forceinline__ float tanh_hw(float x) {
    float y;
    asm("tanh.approx.f32 %0, %1;" : "=f"(y) : "f"(x));
    return y;
}
__device__ __forceinline__ float sigmoid_hw(float x) {
    return fmaf(0.5f, tanh_hw(0.5f * x), 0.5f);
}
__device__ __forceinline__ float sigmoid_fast(float x) {
    float a = fabsf(x);
    float u = __expf(-a);
    float r = __fdividef(1.0f, 1.0f + u);
    return (x >= 0.0f) ? r : u * r;
}
__device__ __forceinline__ float warp_sum(float v) {
    #pragma unroll
    for (int o = 16; o; o >>= 1) v += __shfl_xor_sync(0xffffffff, v, o);
    return v;
}
__device__ __forceinline__ float warp_max(float v) {
    #pragma unroll
    for (int o = 16; o; o >>= 1) v = fmaxf(v, __shfl_xor_sync(0xffffffff, v, o));
    return v;
}

// ---------------------------------------------------------------------------
// Prep: ballots only + counter reset. grid = 192 blocks, 128 threads.
// ---------------------------------------------------------------------------
__global__ __launch_bounds__(128) void prep_kernel(
    const float* __restrict__ tmask, const unsigned char* __restrict__ vpad)
{
    if (blockIdx.x == 0 && threadIdx.x == 0) g_done = 0u;
    int bf = blockIdx.x / 12;       // 0..15
    int rg = blockIdx.x % 12;       // row group of 8
    int b = bf >> 3;
    int tid = threadIdx.x;
    int wp = tid >> 5, lane = tid & 31;
    const float* base = tmask + (size_t)bf * HW;
    const unsigned char* vb = vpad + (size_t)b * HW;

    #pragma unroll
    for (int rr = 0; rr < 2; ++rr) {
        int row = rg * 8 + wp * 2 + rr;
        const float* rp = base + row * WW;
        const unsigned char* vr = vb + row * WW;
        float v0 = rp[lane], v1 = rp[32 + lane], v2 = rp[64 + lane];
        unsigned char q0 = vr[lane], q1 = vr[32 + lane], q2 = vr[64 + lane];
        unsigned t0 = __ballot_sync(0xffffffff, v0 != 0.0f);
        unsigned t1 = __ballot_sync(0xffffffff, v1 != 0.0f);
        unsigned t2 = __ballot_sync(0xffffffff, v2 != 0.0f);
        unsigned p0 = __ballot_sync(0xffffffff, q0 != 0);
        unsigned p1 = __ballot_sync(0xffffffff, q1 != 0);
        unsigned p2 = __ballot_sync(0xffffffff, q2 != 0);
        if (lane == 0) {
            g_meta[bf][row * 3 + 0] = make_uint2(t0, p0);
            g_meta[bf][row * 3 + 1] = make_uint2(t1, p1);
            g_meta[bf][row * 3 + 2] = make_uint2(t2, p2);
        }
    }
}

// ---------------------------------------------------------------------------
// Cost: one block per (b,q). 192 threads = 6 warps; warp owns 16 rows.
// Last finishing block performs the argmin + tail writes.
// ---------------------------------------------------------------------------
__global__ __launch_bounds__(192, 6) void cost_kernel(
    const float* __restrict__ logits,   // (2,8,300,1)
    const float* __restrict__ boxes,    // (2,8,300,4)
    const float* __restrict__ masks,    // (2,8,300,96,96)
    const float* __restrict__ tbox,     // (2,8,4)
    const int*   __restrict__ tvalid,   // (2,8)
    float* __restrict__ C, int out_size)
{
    int blk = blockIdx.x;
    int b = blk / NQ, q = blk % NQ;
    int tid = threadIdx.x;
    int warp = tid >> 5, lane = tid & 31;

    __shared__ float rowFinal[NF * HH];           // 3 KB
    __shared__ float colAll[NF * 3 * 192];        // 18 KB: [f][chunk][warp][lane]
    __shared__ unsigned orAll[NF * 3 * 6];        // target col-OR partials
    __shared__ float red[6][10];
    __shared__ bool isLast;

    float facc = 0.0f, nacc = 0.0f, sacc = 0.0f;

    for (int f = 0; f < NF; ++f) {
        const float* mb = masks + (size_t)((b * NF + f) * NQ + q) * HW + lane;
        const uint2* mt = g_meta[b * NF + f];
        float c0 = -CUDART_INF_F, c1 = -CUDART_INF_F, c2 = -CUDART_INF_F;
        unsigned o0 = 0u, o1 = 0u, o2 = 0u;
        #pragma unroll 2
        for (int r = 0; r < 16; ++r) {
            int row = warp * 16 + r;
            uint2 m0 = mt[row * 3 + 0];
            uint2 m1 = mt[row * 3 + 1];
            uint2 m2 = mt[row * 3 + 2];
            const float* rp = mb + row * WW;
            float x0 = rp[0], x1 = rp[32], x2 = rp[64];
            if ((m0.y >> lane) & 1) x0 = 0.0f;
            if ((m1.y >> lane) & 1) x1 = 0.0f;
            if ((m2.y >> lane) & 1) x2 = 0.0f;
            o0 |= m0.x; o1 |= m1.x; o2 |= m2.x;

            #pragma unroll
            for (int c = 0; c < 3; ++c) {
                float x = (c == 0) ? x0 : (c == 1) ? x1 : x2;
                unsigned tw = (c == 0) ? m0.x : (c == 1) ? m1.x : m2.x;
                bool tb = (tw >> lane) & 1;
                float p = sigmoid_hw(x);
                float omp_ = 1.0f - p;
                float pa = fmaxf(p, omp_);
                float lg = -__logf(pa);
                float ce = fmaxf(tb ? -x : x, 0.0f) + lg;
                float omp = tb ? omp_ : p;
                float at = tb ? 0.25f : 0.75f;
                facc = fmaf(at * ce * omp, omp, facc);
                sacc += p;
                if (tb) nacc += p;
            }
            c0 = fmaxf(c0, x0); c1 = fmaxf(c1, x1); c2 = fmaxf(c2, x2);
            float rm = warp_max(fmaxf(fmaxf(x0, x1), x2));
            if (lane == 0) rowFinal[f * HH + row] = rm;
        }
        colAll[((f * 3 + 0) * 6 + warp) * 32 + lane] = c0;
        colAll[((f * 3 + 1) * 6 + warp) * 32 + lane] = c1;
        colAll[((f * 3 + 2) * 6 + warp) * 32 + lane] = c2;
        if (lane == 0) {
            orAll[(f * 3 + 0) * 6 + warp] = o0;
            orAll[(f * 3 + 1) * 6 + warp] = o1;
            orAll[(f * 3 + 2) * 6 + warp] = o2;
        }
    }
    __syncthreads();

    // projection partials + target stats from bits: 768 rows + 768 cols
    float sx = 0, nx = 0, sy = 0, ny = 0, tsum = 0, txs = 0, tys = 0;
    #pragma unroll
    for (int j = tid; j < NF * HH; j += 192) {
        int f = j / 96, jj = j % 96;
        const uint2* mt = g_meta[b * NF + f];
        uint2 w0 = mt[jj * 3 + 0], w1 = mt[jj * 3 + 1], w2 = mt[jj * 3 + 2];
        tsum += (float)(__popc(w0.x) + __popc(w1.x) + __popc(w2.x));
        float tgx = ((w0.x | w1.x | w2.x) != 0u) ? 1.0f : 0.0f;
        float px = sigmoid_fast(rowFinal[j]);
        sx += px; nx += px * tgx; txs += tgx;

        int c = jj >> 5, l = jj & 31;
        const float* cp = &colAll[((f * 3 + c) * 6) * 32 + l];
        const unsigned* op = &orAll[(f * 3 + c) * 6];
        float m = cp[0];
        unsigned ow = op[0];
        #pragma unroll
        for (int wp = 1; wp < 6; ++wp) { m = fmaxf(m, cp[wp * 32]); ow |= op[wp]; }
        float tgy = ((ow >> l) & 1u) ? 1.0f : 0.0f;
        float py = sigmoid_fast(m);
        sy += py; ny += py * tgy; tys += tgy;
    }

    float v0 = warp_sum(facc), v1 = warp_sum(nacc), v2 = warp_sum(sacc);
    float v3 = warp_sum(sx),   v4 = warp_sum(nx);
    float v5 = warp_sum(sy),   v6 = warp_sum(ny);
    float v7 = warp_sum(tsum), v8 = warp_sum(txs), v9 = warp_sum(tys);
    if (lane == 0) {
        red[warp][0] = v0; red[warp][1] = v1; red[warp][2] = v2;
        red[warp][3] = v3; red[warp][4] = v4; red[warp][5] = v5; red[warp][6] = v6;
        red[warp][7] = v7; red[warp][8] = v8; red[warp][9] = v9;
    }
    __syncthreads();

    if (tid == 0) {
        float A[10];
        #pragma unroll
        for (int i = 0; i < 10; ++i) {
            float t = 0;
            #pragma unroll
            for (int w = 0; w < 6; ++w) t += red[w][i];
            A[i] = t;
        }
        float cost_mask = A[0] / (float)FHW;
        float cost_dice = -((2.0f * A[1] + 1.0f) / (A[2] + A[7] + 1.0f));
        float dx = (2.0f * A[4] + 1.0f) / (A[3] + A[8] + 1.0f);
        float dy = (2.0f * A[6] + 1.0f) / (A[5] + A[9] + 1.0f);
        float cost_proj = -0.5f * (dy + dx);

        float cls = 0, wsum = 0, bbox = 0, giou = 0;
        #pragma unroll
        for (int f = 0; f < NF; ++f) {
            float lg = logits[(b * NF + f) * NQ + q];
            float p = sigmoid_fast(lg);
            float neg = (1.0f - ALPHA_C) * p * p * (-__logf(1.0f - p + EPSV));
            float pos = ALPHA_C * (1.0f - p) * (1.0f - p) * (-__logf(p + EPSV));
            float wv = (tvalid[b * NF + f] != 0) ? 1.0f : 0.0f;
            cls += (pos - neg) * wv; wsum += wv;

            const float* bx = boxes + (size_t)((b * NF + f) * NQ + q) * 4;
            const float* tx = tbox + (size_t)(b * NF + f) * 4;
            bbox += fabsf(bx[0]-tx[0]) + fabsf(bx[1]-tx[1]) + fabsf(bx[2]-tx[2]) + fabsf(bx[3]-tx[3]);

            float sx0 = bx[0]-0.5f*bx[2], sy0 = bx[1]-0.5f*bx[3];
            float sx1 = bx[0]+0.5f*bx[2], sy1 = bx[1]+0.5f*bx[3];
            float tx0 = tx[0]-0.5f*tx[2], ty0 = tx[1]-0.5f*tx[3];
            float tx1 = tx[0]+0.5f*tx[2], ty1 = tx[1]+0.5f*tx[3];
            float a1 = (sx1-sx0)*(sy1-sy0);
            float a2 = (tx1-tx0)*(ty1-ty0);
            float iw = fmaxf(fminf(sx1,tx1) - fmaxf(sx0,tx0), 0.0f);
            float ih = fmaxf(fminf(sy1,ty1) - fmaxf(sy0,ty0), 0.0f);
            float inter = iw * ih;
            float uni = a1 + a2 - inter;
            float iou = inter / uni;
            float cw = fmaxf(fmaxf(sx1,tx1) - fminf(sx0,tx0), 0.0f);
            float ch = fmaxf(fmaxf(sy1,ty1) - fminf(sy0,ty0), 0.0f);
            float ac = cw * ch;
            giou += -(iou - (ac - uni) / ac);
        }
        C[b * NQ + q] = cls / wsum + bbox * (1.0f / NF) + giou * (1.0f / NF)
                      + cost_mask + cost_dice + cost_proj;
    }

    // ---- last block performs argmin + tail writes ----
    if (tid == 0) {
        __threadfence();
        unsigned v = atomicAdd(&g_done, 1u);
        isLast = (v == 2 * NQ - 1);
    }
    __syncthreads();
    if (!isLast) return;
    __threadfence();

    for (int bb = 0; bb < 2; ++bb) {
        float best = CUDART_INF_F; int bi = NQ;
        for (int qq = tid; qq < NQ; qq += 192) {
            float vv = C[bb * NQ + qq];
            if (vv < best || (vv == best && qq < bi)) { best = vv; bi = qq; }
        }
        #pragma unroll
        for (int o = 16; o; o >>= 1) {
            float ov = __shfl_down_sync(0xffffffff, best, o);
            int   oi = __shfl_down_sync(0xffffffff, bi,   o);
            if (ov < best || (ov == best && oi < bi)) { best = ov; bi = oi; }
        }
        __shared__ float sv[6]; __shared__ int si[6];
        if (lane == 0) { sv[warp] = best; si[warp] = bi; }
        __syncthreads();
        if (tid == 0) {
            for (int i = 1; i < 6; ++i) {
                if (sv[i] < best || (sv[i] == best && si[i] < bi)) { best = sv[i]; bi = si[i]; }
            }
            if (out_size >= 608) {
                long long* op = (long long*)(C + 600);
                op[bb] = (long long)bi;
                op[2 + bb] = 0ll;
                if (bb == 0) for (int i = 608; i < out_size; ++i) C[i] = 0.0f;
            } else if (out_size >= 604) {
                C[600 + bb] = (float)bi;
                C[602 + bb] = 0.0f;
                if (bb == 0) for (int i = 604; i < out_size; ++i) C[i] = 0.0f;
            } else {
                if (bb == 0) for (int i = 600; i < out_size; ++i) C[i] = 0.0f;
            }
        }
        __syncthreads();
    }
}

extern "C" void kernel_launch(void* const* d_in, const int* in_sizes, int n_in,
                              void* d_out, int out_size) {
    const float* logits = (const float*)d_in[0];
    const float* boxes  = (const float*)d_in[1];
    const float* masks  = (const float*)d_in[2];
    const float* tmask  = (const float*)d_in[3];
    const float* tbox   = (const float*)d_in[4];
    const int*   tvalid = (const int*)d_in[5];
    const unsigned char* vpad = (const unsigned char*)d_in[6];
    float* out = (float*)d_out;

    prep_kernel<<<192, 128>>>(tmask, vpad);
    cost_kernel<<<2 * NQ, 192>>>(logits, boxes, masks, tbox, tvalid, out, out_size);
}

// round 9
// speedup vs baseline: 1.2926x; 1.0817x over previous
#include <cuda_runtime.h>
#include <math_constants.h>

#define NF 8
#define NQ 300
#define HH 96
#define WW 96
#define HW (HH*WW)        // 9216
#define FHW (NF*HW)       // 73728
#define ALPHA_C 0.25f
#define EPSV 1e-8f
#define LN2F 0.69314718056f

// bits per (b,f,row,chunk): {tmask bits, vpad bits}
__device__ uint2 g_meta[16][HH*3];
__device__ unsigned g_done;

__device__ __forceinline__ float tanh_hw(float x) {
    float y;
    asm("tanh.approx.f32 %0, %1;" : "=f"(y) : "f"(x));
    return y;
}
__device__ __forceinline__ float sigmoid_fast(float x) {
    float a = fabsf(x);
    float u = __expf(-a);
    float r = __fdividef(1.0f, 1.0f + u);
    return (x >= 0.0f) ? r : u * r;
}
__device__ __forceinline__ float warp_sum(float v) {
    #pragma unroll
    for (int o = 16; o; o >>= 1) v += __shfl_xor_sync(0xffffffff, v, o);
    return v;
}
__device__ __forceinline__ float warp_max(float v) {
    #pragma unroll
    for (int o = 16; o; o >>= 1) v = fmaxf(v, __shfl_xor_sync(0xffffffff, v, o));
    return v;
}

// ---------------------------------------------------------------------------
// Prep: ballots only + counter reset. grid = 192 blocks, 128 threads.
// ---------------------------------------------------------------------------
__global__ __launch_bounds__(128) void prep_kernel(
    const float* __restrict__ tmask, const unsigned char* __restrict__ vpad)
{
    if (blockIdx.x == 0 && threadIdx.x == 0) g_done = 0u;
    int bf = blockIdx.x / 12;       // 0..15
    int rg = blockIdx.x % 12;       // row group of 8
    int b = bf >> 3;
    int tid = threadIdx.x;
    int wp = tid >> 5, lane = tid & 31;
    const float* base = tmask + (size_t)bf * HW;
    const unsigned char* vb = vpad + (size_t)b * HW;

    #pragma unroll
    for (int rr = 0; rr < 2; ++rr) {
        int row = rg * 8 + wp * 2 + rr;
        const float* rp = base + row * WW;
        const unsigned char* vr = vb + row * WW;
        float v0 = rp[lane], v1 = rp[32 + lane], v2 = rp[64 + lane];
        unsigned char q0 = vr[lane], q1 = vr[32 + lane], q2 = vr[64 + lane];
        unsigned t0 = __ballot_sync(0xffffffff, v0 != 0.0f);
        unsigned t1 = __ballot_sync(0xffffffff, v1 != 0.0f);
        unsigned t2 = __ballot_sync(0xffffffff, v2 != 0.0f);
        unsigned p0 = __ballot_sync(0xffffffff, q0 != 0);
        unsigned p1 = __ballot_sync(0xffffffff, q1 != 0);
        unsigned p2 = __ballot_sync(0xffffffff, q2 != 0);
        if (lane == 0) {
            g_meta[bf][row * 3 + 0] = make_uint2(t0, p0);
            g_meta[bf][row * 3 + 1] = make_uint2(t1, p1);
            g_meta[bf][row * 3 + 2] = make_uint2(t2, p2);
        }
    }
}

// ---------------------------------------------------------------------------
// Cost: one block per (b,q). 192 threads = 6 warps; warp owns 16 rows.
// tanh-space focal math. Last block performs argmin + tail writes.
// ---------------------------------------------------------------------------
__global__ __launch_bounds__(192, 5) void cost_kernel(
    const float* __restrict__ logits,   // (2,8,300,1)
    const float* __restrict__ boxes,    // (2,8,300,4)
    const float* __restrict__ masks,    // (2,8,300,96,96)
    const float* __restrict__ tbox,     // (2,8,4)
    const int*   __restrict__ tvalid,   // (2,8)
    float* __restrict__ C, int out_size)
{
    int blk = blockIdx.x;
    int b = blk / NQ, q = blk % NQ;
    int tid = threadIdx.x;
    int warp = tid >> 5, lane = tid & 31;
    unsigned bitm = 1u << lane;

    __shared__ float rowFinal[NF * HH];           // 3 KB
    __shared__ float colAll[NF * 3 * 192];        // 18 KB
    __shared__ unsigned orAll[NF * 3 * 6];
    __shared__ float red[6][10];
    __shared__ bool isLast;

    float facc = 0.0f, nacc = 0.0f, sacc = 0.0f;  // nacc/sacc in th-space

    for (int f = 0; f < NF; ++f) {
        const float* mb = masks + (size_t)((b * NF + f) * NQ + q) * HW + lane;
        const uint2* mt = g_meta[b * NF + f];
        float c0 = -CUDART_INF_F, c1 = -CUDART_INF_F, c2 = -CUDART_INF_F;
        unsigned o0 = 0u, o1 = 0u, o2 = 0u;
        #pragma unroll 4
        for (int r = 0; r < 16; ++r) {
            int row = warp * 16 + r;
            uint2 m0 = mt[row * 3 + 0];
            uint2 m1 = mt[row * 3 + 1];
            uint2 m2 = mt[row * 3 + 2];
            const float* rp = mb + row * WW;
            float x0 = rp[0], x1 = rp[32], x2 = rp[64];
            if (m0.y & bitm) x0 = 0.0f;
            if (m1.y & bitm) x1 = 0.0f;
            if (m2.y & bitm) x2 = 0.0f;
            o0 |= m0.x; o1 |= m1.x; o2 |= m2.x;

            #pragma unroll
            for (int c = 0; c < 3; ++c) {
                float x = (c == 0) ? x0 : (c == 1) ? x1 : x2;
                unsigned tw = (c == 0) ? m0.x : (c == 1) ? m1.x : m2.x;
                bool tb = (tw & bitm) != 0u;
                float th = tanh_hw(0.5f * x);          // MUFU
                float lg2v = __log2f(1.0f + fabsf(th)); // MUFU
                float xs = tb ? -x : x;
                float m = fmaxf(xs, 0.0f);
                float ce = fmaf(-LN2F, lg2v, m + LN2F); // BCE
                float u = tb ? th : -th;
                float omu = 1.0f - u;                  // 2*(1-p_t)
                float at4 = tb ? 0.0625f : 0.1875f;    // alpha_t/4
                facc = fmaf(ce * omu * omu, at4, facc);
                sacc += th;
                if (tb) nacc += th;
            }
            c0 = fmaxf(c0, x0); c1 = fmaxf(c1, x1); c2 = fmaxf(c2, x2);
            float rm = warp_max(fmaxf(fmaxf(x0, x1), x2));
            if (lane == 0) rowFinal[f * HH + row] = rm;
        }
        colAll[((f * 3 + 0) * 6 + warp) * 32 + lane] = c0;
        colAll[((f * 3 + 1) * 6 + warp) * 32 + lane] = c1;
        colAll[((f * 3 + 2) * 6 + warp) * 32 + lane] = c2;
        if (lane == 0) {
            orAll[(f * 3 + 0) * 6 + warp] = o0;
            orAll[(f * 3 + 1) * 6 + warp] = o1;
            orAll[(f * 3 + 2) * 6 + warp] = o2;
        }
    }
    __syncthreads();

    // projection partials + target stats from bits
    float sx = 0, nx = 0, sy = 0, ny = 0, tsum = 0, txs = 0, tys = 0;
    #pragma unroll
    for (int j = tid; j < NF * HH; j += 192) {
        int f = j / 96, jj = j % 96;
        const uint2* mt = g_meta[b * NF + f];
        uint2 w0 = mt[jj * 3 + 0], w1 = mt[jj * 3 + 1], w2 = mt[jj * 3 + 2];
        tsum += (float)(__popc(w0.x) + __popc(w1.x) + __popc(w2.x));
        float tgx = ((w0.x | w1.x | w2.x) != 0u) ? 1.0f : 0.0f;
        float px = sigmoid_fast(rowFinal[j]);
        sx += px; nx += px * tgx; txs += tgx;

        int c = jj >> 5, l = jj & 31;
        const float* cp = &colAll[((f * 3 + c) * 6) * 32 + l];
        const unsigned* op = &orAll[(f * 3 + c) * 6];
        float m = cp[0];
        unsigned ow = op[0];
        #pragma unroll
        for (int wp = 1; wp < 6; ++wp) { m = fmaxf(m, cp[wp * 32]); ow |= op[wp]; }
        float tgy = ((ow >> l) & 1u) ? 1.0f : 0.0f;
        float py = sigmoid_fast(m);
        sy += py; ny += py * tgy; tys += tgy;
    }

    float v0 = warp_sum(facc), v1 = warp_sum(nacc), v2 = warp_sum(sacc);
    float v3 = warp_sum(sx),   v4 = warp_sum(nx);
    float v5 = warp_sum(sy),   v6 = warp_sum(ny);
    float v7 = warp_sum(tsum), v8 = warp_sum(txs), v9 = warp_sum(tys);
    if (lane == 0) {
        red[warp][0] = v0; red[warp][1] = v1; red[warp][2] = v2;
        red[warp][3] = v3; red[warp][4] = v4; red[warp][5] = v5; red[warp][6] = v6;
        red[warp][7] = v7; red[warp][8] = v8; red[warp][9] = v9;
    }
    __syncthreads();

    if (tid == 0) {
        float A[10];
        #pragma unroll
        for (int i = 0; i < 10; ++i) {
            float t = 0;
            #pragma unroll
            for (int w = 0; w < 6; ++w) t += red[w][i];
            A[i] = t;
        }
        // reconstruct true p-sums from th-sums
        float naccr = 0.5f * (A[7] + A[1]);       // sum_{t} p
        float saccr = 0.5f * ((float)FHW + A[2]); // sum p
        float cost_mask = A[0] / (float)FHW;
        float cost_dice = -((2.0f * naccr + 1.0f) / (saccr + A[7] + 1.0f));
        float dx = (2.0f * A[4] + 1.0f) / (A[3] + A[8] + 1.0f);
        float dy = (2.0f * A[6] + 1.0f) / (A[5] + A[9] + 1.0f);
        float cost_proj = -0.5f * (dy + dx);

        float cls = 0, wsum = 0, bbox = 0, giou = 0;
        #pragma unroll
        for (int f = 0; f < NF; ++f) {
            float lg = logits[(b * NF + f) * NQ + q];
            float p = sigmoid_fast(lg);
            float neg = (1.0f - ALPHA_C) * p * p * (-__logf(1.0f - p + EPSV));
            float pos = ALPHA_C * (1.0f - p) * (1.0f - p) * (-__logf(p + EPSV));
            float wv = (tvalid[b * NF + f] != 0) ? 1.0f : 0.0f;
            cls += (pos - neg) * wv; wsum += wv;

            const float* bx = boxes + (size_t)((b * NF + f) * NQ + q) * 4;
            const float* tx = tbox + (size_t)(b * NF + f) * 4;
            bbox += fabsf(bx[0]-tx[0]) + fabsf(bx[1]-tx[1]) + fabsf(bx[2]-tx[2]) + fabsf(bx[3]-tx[3]);

            float sx0 = bx[0]-0.5f*bx[2], sy0 = bx[1]-0.5f*bx[3];
            float sx1 = bx[0]+0.5f*bx[2], sy1 = bx[1]+0.5f*bx[3];
            float tx0 = tx[0]-0.5f*tx[2], ty0 = tx[1]-0.5f*tx[3];
            float tx1 = tx[0]+0.5f*tx[2], ty1 = tx[1]+0.5f*tx[3];
            float a1 = (sx1-sx0)*(sy1-sy0);
            float a2 = (tx1-tx0)*(ty1-ty0);
            float iw = fmaxf(fminf(sx1,tx1) - fmaxf(sx0,tx0), 0.0f);
            float ih = fmaxf(fminf(sy1,ty1) - fmaxf(sy0,ty0), 0.0f);
            float inter = iw * ih;
            float uni = a1 + a2 - inter;
            float iou = inter / uni;
            float cw = fmaxf(fmaxf(sx1,tx1) - fminf(sx0,tx0), 0.0f);
            float ch = fmaxf(fmaxf(sy1,ty1) - fminf(sy0,ty0), 0.0f);
            float ac = cw * ch;
            giou += -(iou - (ac - uni) / ac);
        }
        C[b * NQ + q] = cls / wsum + bbox * (1.0f / NF) + giou * (1.0f / NF)
                      + cost_mask + cost_dice + cost_proj;
    }

    // ---- last block performs argmin + tail writes ----
    if (tid == 0) {
        __threadfence();
        unsigned v = atomicAdd(&g_done, 1u);
        isLast = (v == 2 * NQ - 1);
    }
    __syncthreads();
    if (!isLast) return;
    __threadfence();

    for (int bb = 0; bb < 2; ++bb) {
        float best = CUDART_INF_F; int bi = NQ;
        for (int qq = tid; qq < NQ; qq += 192) {
            float vv = C[bb * NQ + qq];
            if (vv < best || (vv == best && qq < bi)) { best = vv; bi = qq; }
        }
        #pragma unroll
        for (int o = 16; o; o >>= 1) {
            float ov = __shfl_down_sync(0xffffffff, best, o);
            int   oi = __shfl_down_sync(0xffffffff, bi,   o);
            if (ov < best || (ov == best && oi < bi)) { best = ov; bi = oi; }
        }
        __shared__ float sv[6]; __shared__ int si[6];
        if (lane == 0) { sv[warp] = best; si[warp] = bi; }
        __syncthreads();
        if (tid == 0) {
            for (int i = 1; i < 6; ++i) {
                if (sv[i] < best || (sv[i] == best && si[i] < bi)) { best = sv[i]; bi = si[i]; }
            }
            if (out_size >= 608) {
                long long* op = (long long*)(C + 600);
                op[bb] = (long long)bi;
                op[2 + bb] = 0ll;
                if (bb == 0) for (int i = 608; i < out_size; ++i) C[i] = 0.0f;
            } else if (out_size >= 604) {
                C[600 + bb] = (float)bi;
                C[602 + bb] = 0.0f;
                if (bb == 0) for (int i = 604; i < out_size; ++i) C[i] = 0.0f;
            } else {
                if (bb == 0) for (int i = 600; i < out_size; ++i) C[i] = 0.0f;
            }
        }
        __syncthreads();
    }
}

extern "C" void kernel_launch(void* const* d_in, const int* in_sizes, int n_in,
                              void* d_out, int out_size) {
    const float* logits = (const float*)d_in[0];
    const float* boxes  = (const float*)d_in[1];
    const float* masks  = (const float*)d_in[2];
    const float* tmask  = (const float*)d_in[3];
    const float* tbox   = (const float*)d_in[4];
    const int*   tvalid = (const int*)d_in[5];
    const unsigned char* vpad = (const unsigned char*)d_in[6];
    float* out = (float*)d_out;

    prep_kernel<<<192, 128>>>(tmask, vpad);
    cost_kernel<<<2 * NQ, 192>>>(logits, boxes, masks, tbox, tvalid, out, out_size);
}